// round 11
// baseline (speedup 1.0000x reference)
#include <cuda_runtime.h>
#include <cuda_fp16.h>

// IntDVF scaling-and-squaring, packed-half4, 2-voxels-per-thread version.
// ddf0 = dvf / 2^7 ; repeat 7x: ddf = ddf + warp(ddf, ddf)
//
// Field stored as 4x fp16 (x,y,z,pad) = 8B/voxel. Each thread handles an
// adjacent z-pair: one LDG.128 center read + one STG.128 store per pair,
// 16 independent gather LDG.64s in flight. Location-clamping replaces index
// clipping (mathematically identical for trilinear with clipped indices).
// All arithmetic fp32; fp16 is storage only. Final step writes fp32 AoS.

#define D     128
#define D2    (D * D)
#define D3    (D * D * D)
#define NVOX  (2 * D3)          // 4,194,304 voxels (batch=2)
#define NPAIR (NVOX / 2)
#define NT    256

// Two 33.5 MB packed ping-pong buffers (16B-aligned for paired access).
__device__ uint4 g_a[(size_t)NPAIR];
__device__ uint4 g_b[(size_t)NPAIR];

__device__ __forceinline__ uint2 packh4(float x, float y, float z) {
    __half2 xy = __floats2half2_rn(x, y);
    __half2 zw = __floats2half2_rn(z, 0.0f);
    uint2 r;
    r.x = *(const unsigned int*)&xy;
    r.y = *(const unsigned int*)&zw;
    return r;
}

__device__ __forceinline__ void unpackh4(unsigned int vx, unsigned int vy,
                                         float& x, float& y, float& z) {
    __half2 xy = *(const __half2*)&vx;
    __half2 zw = *(const __half2*)&vy;
    float2 f = __half22float2(xy);
    x = f.x;
    y = f.y;
    z = __half2float(__low2half(zw));
}

__global__ __launch_bounds__(NT)
void pack_h4p(const float* __restrict__ in, uint4* __restrict__ out) {
    int ip = blockIdx.x * NT + threadIdx.x;      // voxel-pair index
    const float2* p = (const float2*)in + (size_t)3 * ip;
    float2 f0 = p[0], f1 = p[1], f2 = p[2];
    uint2 v0 = packh4(f0.x, f0.y, f1.x);
    uint2 v1 = packh4(f1.y, f2.x, f2.y);
    out[ip] = make_uint4(v0.x, v0.y, v1.x, v1.y);
}

// One trilinear sample + integration for a single voxel.
template<bool SCALED>
__device__ __forceinline__ float3 sample_one(
    const uint2* __restrict__ src, int bb,
    float xf, float yf, float zf,
    float rx, float ry, float rz, float scale)
{
    float lx = xf + (SCALED ? rx * scale : rx);
    float ly = yf + (SCALED ? ry * scale : ry);
    float lz = zf + (SCALED ? rz * scale : rz);

    // Clamp the location (equivalent to reference's index clipping).
    lx = fminf(fmaxf(lx, 0.0f), 127.0f);
    ly = fminf(fmaxf(ly, 0.0f), 127.0f);
    lz = fminf(fmaxf(lz, 0.0f), 127.0f);

    float fx = floorf(lx), fy = floorf(ly), fz = floorf(lz);
    float wx1 = lx - fx, wy1 = ly - fy, wz1 = lz - fz;
    float wx0 = 1.0f - wx1, wy0 = 1.0f - wy1, wz0 = 1.0f - wz1;

    int jx = (int)fx, jy = (int)fy, jz = (int)fz;     // all in [0,127]
    int ix1 = min(jx + 1, D - 1);
    int iy1 = min(jy + 1, D - 1);
    int iz1 = min(jz + 1, D - 1);

    int p00 = bb + jx  * D2 + jy  * D;
    int p01 = bb + jx  * D2 + iy1 * D;
    int p10 = bb + ix1 * D2 + jy  * D;
    int p11 = bb + ix1 * D2 + iy1 * D;

    uint2 v000 = __ldg(src + p00 + jz);
    uint2 v001 = __ldg(src + p00 + iz1);
    uint2 v010 = __ldg(src + p01 + jz);
    uint2 v011 = __ldg(src + p01 + iz1);
    uint2 v100 = __ldg(src + p10 + jz);
    uint2 v101 = __ldg(src + p10 + iz1);
    uint2 v110 = __ldg(src + p11 + jz);
    uint2 v111 = __ldg(src + p11 + iz1);

    float w00 = wx0 * wy0, w01 = wx0 * wy1, w10 = wx1 * wy0, w11 = wx1 * wy1;
    float w000 = w00 * wz0, w001 = w00 * wz1;
    float w010 = w01 * wz0, w011 = w01 * wz1;
    float w100 = w10 * wz0, w101 = w10 * wz1;
    float w110 = w11 * wz0, w111 = w11 * wz1;

    float ax = 0.f, ay = 0.f, az = 0.f, tx, ty, tz;
    unpackh4(v000.x, v000.y, tx, ty, tz); ax = fmaf(w000, tx, ax); ay = fmaf(w000, ty, ay); az = fmaf(w000, tz, az);
    unpackh4(v001.x, v001.y, tx, ty, tz); ax = fmaf(w001, tx, ax); ay = fmaf(w001, ty, ay); az = fmaf(w001, tz, az);
    unpackh4(v010.x, v010.y, tx, ty, tz); ax = fmaf(w010, tx, ax); ay = fmaf(w010, ty, ay); az = fmaf(w010, tz, az);
    unpackh4(v011.x, v011.y, tx, ty, tz); ax = fmaf(w011, tx, ax); ay = fmaf(w011, ty, ay); az = fmaf(w011, tz, az);
    unpackh4(v100.x, v100.y, tx, ty, tz); ax = fmaf(w100, tx, ax); ay = fmaf(w100, ty, ay); az = fmaf(w100, tz, az);
    unpackh4(v101.x, v101.y, tx, ty, tz); ax = fmaf(w101, tx, ax); ay = fmaf(w101, ty, ay); az = fmaf(w101, tz, az);
    unpackh4(v110.x, v110.y, tx, ty, tz); ax = fmaf(w110, tx, ax); ay = fmaf(w110, ty, ay); az = fmaf(w110, tz, az);
    unpackh4(v111.x, v111.y, tx, ty, tz); ax = fmaf(w111, tx, ax); ay = fmaf(w111, ty, ay); az = fmaf(w111, tz, az);

    float3 o;
    if (SCALED) {
        o.x = scale * (rx + ax);
        o.y = scale * (ry + ay);
        o.z = scale * (rz + az);
    } else {
        o.x = rx + ax;
        o.y = ry + ay;
        o.z = rz + az;
    }
    return o;
}

template<bool OUT_F32_AOS, bool SCALED>
__global__ __launch_bounds__(NT)
void intdvf_step(const uint4* __restrict__ srcp, void* __restrict__ dst_raw,
                 float scale) {
    int ip = blockIdx.x * NT + threadIdx.x;      // voxel-pair index
    int idx = ip * 2;                            // even voxel of the pair
    int z = idx & (D - 1);                       // even
    int y = (idx >> 7) & (D - 1);
    int x = (idx >> 14) & (D - 1);
    int bb = (idx >> 21) * D3;

    uint4 c = __ldg(srcp + ip);                  // centers for both voxels (16B)
    float rx0, ry0, rz0, rx1, ry1, rz1;
    unpackh4(c.x, c.y, rx0, ry0, rz0);
    unpackh4(c.z, c.w, rx1, ry1, rz1);

    const uint2* __restrict__ src = (const uint2*)srcp;
    float xf = (float)x, yf = (float)y, zf = (float)z;

    float3 o0 = sample_one<SCALED>(src, bb, xf, yf, zf,          rx0, ry0, rz0, scale);
    float3 o1 = sample_one<SCALED>(src, bb, xf, yf, zf + 1.0f,   rx1, ry1, rz1, scale);

    if (OUT_F32_AOS) {
        float2* dst = (float2*)dst_raw + (size_t)3 * ip;
        dst[0] = make_float2(o0.x, o0.y);
        dst[1] = make_float2(o0.z, o1.x);
        dst[2] = make_float2(o1.y, o1.z);
    } else {
        uint2 p0 = packh4(o0.x, o0.y, o0.z);
        uint2 p1 = packh4(o1.x, o1.y, o1.z);
        ((uint4*)dst_raw)[ip] = make_uint4(p0.x, p0.y, p1.x, p1.y);
    }
}

extern "C" void kernel_launch(void* const* d_in, const int* in_sizes, int n_in,
                              void* d_out, int out_size) {
    const float* dvf = (const float*)d_in[0];

    uint4* A = nullptr;
    uint4* Bf = nullptr;
    cudaGetSymbolAddress((void**)&A,  g_a);
    cudaGetSymbolAddress((void**)&Bf, g_b);

    const int nblocks = NPAIR / NT;              // 8192
    const float s0 = 1.0f / 128.0f;              // 1 / 2^NUM_STEPS

    pack_h4p<<<nblocks, NT>>>(dvf, A);

    intdvf_step<false, true ><<<nblocks, NT>>>(A,  Bf,   s0);   // step 1 (fused /128)
    intdvf_step<false, false><<<nblocks, NT>>>(Bf, A,    1.0f); // step 2
    intdvf_step<false, false><<<nblocks, NT>>>(A,  Bf,   1.0f); // step 3
    intdvf_step<false, false><<<nblocks, NT>>>(Bf, A,    1.0f); // step 4
    intdvf_step<false, false><<<nblocks, NT>>>(A,  Bf,   1.0f); // step 5
    intdvf_step<false, false><<<nblocks, NT>>>(Bf, A,    1.0f); // step 6
    intdvf_step<true,  false><<<nblocks, NT>>>(A,  d_out, 1.0f); // step 7 -> fp32 AoS
}